// round 4
// baseline (speedup 1.0000x reference)
#include <cuda_runtime.h>
#include <math.h>

#define BB   512
#define TT   128
#define DIN  256
#define HH   1024
#define G4   4096          // 4*HH
#define MTOT (TT*BB)       // 65536

// ---------------- scratch (device globals: no allocations allowed) ----------
__device__ float g_X [(size_t)TT * BB * G4];   // 1 GiB: gate pre-activations, reused per layer
__device__ float g_H1[(size_t)TT * BB * HH];   // 256 MB: layer-1 hidden history
__device__ float g_H2[(size_t)TT * BB * HH];   // 256 MB: layer-2 hidden history
__device__ float g_c [BB * HH];                // cell state (reused per layer)
__device__ float g_zero[BB * HH];              // never written -> stays zero (h_{-1})

// ---------------- fp32x2 packed-FMA helpers (Blackwell) ---------------------
__device__ __forceinline__ unsigned long long dup2(float a) {
    unsigned long long r;
    asm("mov.b64 %0, {%1, %1};" : "=l"(r) : "r"(__float_as_uint(a)));
    return r;
}
__device__ __forceinline__ void ffma2(unsigned long long& d,
                                      unsigned long long a,
                                      unsigned long long b) {
    asm("fma.rn.f32x2 %0, %1, %2, %0;" : "+l"(d) : "l"(a), "l"(b));
}
__device__ __forceinline__ float lo2(unsigned long long v) { return __uint_as_float((unsigned)v); }
__device__ __forceinline__ float hi2(unsigned long long v) { return __uint_as_float((unsigned)(v >> 32)); }
__device__ __forceinline__ float sigmoidf_(float x) { return 1.f / (1.f + expf(-x)); }

// ============================================================================
// Big GEMM: g_X[m][n] = A[m][:] @ W[:, n] + bias[n]
//   m = t*BB + b.  CHARS=true: A row maps to chars[b][t][:] (K=256)
//   CHARS=false: A = g_H1, row m*HH (K=1024)
// Tiling: 128x128 C-tile, Kt=16, 256 threads, 8x8 per-thread microtile (FFMA2)
// ============================================================================
template<int KD, bool CHARS>
__global__ __launch_bounds__(256, 2)
void gemm_bias_kernel(const float* __restrict__ A,
                      const float* __restrict__ W,
                      const float* __restrict__ bias)
{
    __shared__ __align__(16) float As[16][132];  // [k][m], padded vs bank conflicts
    __shared__ __align__(16) float Bs[16][128];  // [k][n]

    const int tid = threadIdx.x;
    const int tx  = tid & 15;
    const int ty  = tid >> 4;
    const int n0  = blockIdx.x * 128;
    const int m0  = blockIdx.y * 128;

    const float* Abase = CHARS ? A : g_H1;

    unsigned long long acc[8][4];
    #pragma unroll
    for (int i = 0; i < 8; i++)
        #pragma unroll
        for (int p = 0; p < 4; p++) acc[i][p] = 0ull;

    const int a_k = tid & 15;     // k within tile (contiguous global reads)
    const int a_m = tid >> 4;     // base m (0..15), +16*r
    const int b_c = tid & 127;    // col 0..127 (contiguous global reads)
    const int b_k = tid >> 7;     // 0..1, +2*r

    for (int kt = 0; kt < KD; kt += 16) {
        #pragma unroll
        for (int r = 0; r < 8; r++) {
            int m = m0 + a_m + 16 * r;
            size_t row = CHARS ? ((size_t)(m & 511) * TT + (m >> 9)) * KD
                               : (size_t)m * KD;
            As[a_k][a_m + 16 * r] = Abase[row + kt + a_k];
        }
        #pragma unroll
        for (int r = 0; r < 8; r++) {
            int k = b_k + 2 * r;
            Bs[k][b_c] = W[(size_t)(kt + k) * G4 + n0 + b_c];
        }
        __syncthreads();

        #pragma unroll
        for (int k = 0; k < 16; k++) {
            float4 a0 = *(const float4*)&As[k][ty * 4];
            float4 a1 = *(const float4*)&As[k][64 + ty * 4];
            unsigned long long bp[4];
            bp[0] = *(const unsigned long long*)&Bs[k][tx * 4];
            bp[1] = *(const unsigned long long*)&Bs[k][tx * 4 + 2];
            bp[2] = *(const unsigned long long*)&Bs[k][64 + tx * 4];
            bp[3] = *(const unsigned long long*)&Bs[k][64 + tx * 4 + 2];
            float av[8] = {a0.x, a0.y, a0.z, a0.w, a1.x, a1.y, a1.z, a1.w};
            #pragma unroll
            for (int i = 0; i < 8; i++) {
                unsigned long long ad = dup2(av[i]);
                #pragma unroll
                for (int p = 0; p < 4; p++) ffma2(acc[i][p], ad, bp[p]);
            }
        }
        __syncthreads();
    }

    #pragma unroll
    for (int i = 0; i < 8; i++) {
        int m = m0 + ((i < 4) ? (ty * 4 + i) : (64 + ty * 4 + i - 4));
        #pragma unroll
        for (int q = 0; q < 2; q++) {
            int n = n0 + q * 64 + tx * 4;
            float4 v;
            v.x = lo2(acc[i][q * 2])     + bias[n + 0];
            v.y = hi2(acc[i][q * 2])     + bias[n + 1];
            v.z = lo2(acc[i][q * 2 + 1]) + bias[n + 2];
            v.w = hi2(acc[i][q * 2 + 1]) + bias[n + 3];
            *(float4*)&g_X[(size_t)m * G4 + n] = v;
        }
    }
}

// ============================================================================
// Fused LSTM step: z = X_t + h_{t-1}@U; gates; c,h update.
// Block computes 128(batch) x 32(hidden j) x 4(gates) = 128x128 effective tile.
// Gate columns {j, H+j, 2H+j, 3H+j} are 4 contiguous 128B segments per k-row.
// grid = (HH/32, BB/128) = (32, 4)
// ============================================================================
__global__ __launch_bounds__(256, 2)
void lstm_step_kernel(const float* __restrict__ U, int t, int layer)
{
    __shared__ __align__(16) float As[16][132];
    __shared__ __align__(16) float Bs[16][128];   // [k][gate*32 + j]

    const int tid = threadIdx.x;
    const int tx  = tid & 15;
    const int ty  = tid >> 4;
    const int j0  = blockIdx.x * 32;
    const int m0  = blockIdx.y * 128;

    const float* Hbuf = layer ? g_H2 : g_H1;
    const float* h_in = (t == 0) ? g_zero : (Hbuf + (size_t)(t - 1) * BB * HH);
    float*       h_out = (float*)(Hbuf + (size_t)t * BB * HH);
    const float* X_t  = g_X + (size_t)t * BB * G4;

    unsigned long long acc[8][4];   // [m-sub][gate] packed pair over (j, j+1)
    #pragma unroll
    for (int i = 0; i < 8; i++)
        #pragma unroll
        for (int g = 0; g < 4; g++) acc[i][g] = 0ull;

    const int a_k = tid & 15;
    const int a_m = tid >> 4;
    const int b_c = tid & 127;
    const int b_k = tid >> 7;
    const int bg  = b_c >> 5;     // gate for B load
    const int bj  = b_c & 31;     // j offset for B load

    for (int kt = 0; kt < HH; kt += 16) {
        #pragma unroll
        for (int r = 0; r < 8; r++)
            As[a_k][a_m + 16 * r] =
                h_in[(size_t)(m0 + a_m + 16 * r) * HH + kt + a_k];
        #pragma unroll
        for (int r = 0; r < 8; r++) {
            int k = b_k + 2 * r;
            Bs[k][b_c] = U[(size_t)(kt + k) * G4 + bg * HH + j0 + bj];
        }
        __syncthreads();

        #pragma unroll
        for (int k = 0; k < 16; k++) {
            float4 a0 = *(const float4*)&As[k][ty * 4];
            float4 a1 = *(const float4*)&As[k][64 + ty * 4];
            unsigned long long bp[4];
            #pragma unroll
            for (int g = 0; g < 4; g++)
                bp[g] = *(const unsigned long long*)&Bs[k][g * 32 + tx * 2];
            float av[8] = {a0.x, a0.y, a0.z, a0.w, a1.x, a1.y, a1.z, a1.w};
            #pragma unroll
            for (int i = 0; i < 8; i++) {
                unsigned long long ad = dup2(av[i]);
                #pragma unroll
                for (int g = 0; g < 4; g++) ffma2(acc[i][g], ad, bp[g]);
            }
        }
        __syncthreads();
    }

    // Epilogue: gates + state update. c is thread-exclusive (same (m,j) owner
    // every step); h_out buffer differs from h_in buffer -> no races.
    #pragma unroll
    for (int i = 0; i < 8; i++) {
        int m = m0 + ((i < 4) ? (ty * 4 + i) : (64 + ty * 4 + i - 4));
        const float* Xrow = X_t + (size_t)m * G4;
        #pragma unroll
        for (int jj = 0; jj < 2; jj++) {
            int j = j0 + tx * 2 + jj;
            float zi = (jj ? hi2(acc[i][0]) : lo2(acc[i][0])) + Xrow[j];
            float zf = (jj ? hi2(acc[i][1]) : lo2(acc[i][1])) + Xrow[HH + j];
            float zg = (jj ? hi2(acc[i][2]) : lo2(acc[i][2])) + Xrow[2 * HH + j];
            float zo = (jj ? hi2(acc[i][3]) : lo2(acc[i][3])) + Xrow[3 * HH + j];
            float ig = sigmoidf_(zi);
            float fg = sigmoidf_(zf);
            float gg = tanhf(zg);
            float og = sigmoidf_(zo);
            size_t cidx = (size_t)m * HH + j;
            float c = fg * g_c[cidx] + ig * gg;
            g_c[cidx]   = c;
            h_out[cidx] = og * tanhf(c);
        }
    }
}

// ---------------- small kernels ---------------------------------------------
__global__ void zero_c_kernel()
{
    int i = blockIdx.x * blockDim.x + threadIdx.x;
    if (i < BB * HH) g_c[i] = 0.f;
}

__global__ void dense_out_kernel(const int* __restrict__ seq,
                                 const float* __restrict__ Wd,
                                 const float* __restrict__ bd,
                                 float* __restrict__ out)
{
    int b   = blockIdx.x;
    int tid = threadIdx.x;   // 128 threads
    const float* hrow = g_H2 + ((size_t)(seq[b] - 1) * BB + b) * HH;
    float s0 = 0.f, s1 = 0.f, s2 = 0.f;
    for (int j = tid; j < HH; j += 128) {
        float h = hrow[j];
        s0 += h * Wd[j * 3 + 0];
        s1 += h * Wd[j * 3 + 1];
        s2 += h * Wd[j * 3 + 2];
    }
    __shared__ float sm[3][128];
    sm[0][tid] = s0; sm[1][tid] = s1; sm[2][tid] = s2;
    __syncthreads();
    for (int s = 64; s > 0; s >>= 1) {
        if (tid < s) {
            sm[0][tid] += sm[0][tid + s];
            sm[1][tid] += sm[1][tid + s];
            sm[2][tid] += sm[2][tid + s];
        }
        __syncthreads();
    }
    if (tid == 0) {
        out[b * 3 + 0] = fmaxf(sm[0][0] + bd[0], 0.f);
        out[b * 3 + 1] = fmaxf(sm[1][0] + bd[1], 0.f);
        out[b * 3 + 2] = fmaxf(sm[2][0] + bd[2], 0.f);
    }
}

// ---------------- launch -----------------------------------------------------
extern "C" void kernel_launch(void* const* d_in, const int* in_sizes, int n_in,
                              void* d_out, int out_size)
{
    const float* chars = (const float*)d_in[0];
    const int*   seq   = (const int*)  d_in[1];
    const float* W1    = (const float*)d_in[2];
    const float* U1    = (const float*)d_in[3];
    const float* b1    = (const float*)d_in[4];
    const float* W2    = (const float*)d_in[5];
    const float* U2    = (const float*)d_in[6];
    const float* b2    = (const float*)d_in[7];
    const float* Wd    = (const float*)d_in[8];
    const float* bd    = (const float*)d_in[9];
    float*       out   = (float*)d_out;

    dim3 blk(256);
    dim3 gX(G4 / 128, MTOT / 128);   // 32 x 512
    dim3 gS(HH / 32, BB / 128);      // 32 x 4

    // Layer 1: X = chars@W1 + b1 (all timesteps), then 128 recurrent steps
    gemm_bias_kernel<DIN, true><<<gX, blk>>>(chars, W1, b1);
    zero_c_kernel<<<(BB * HH + 255) / 256, 256>>>();
    for (int t = 0; t < TT; t++)
        lstm_step_kernel<<<gS, blk>>>(U1, t, 0);

    // Layer 2: X = H1@W2 + b2 (reuses g_X), then 128 recurrent steps
    gemm_bias_kernel<HH, false><<<gX, blk>>>(nullptr, W2, b2);
    zero_c_kernel<<<(BB * HH + 255) / 256, 256>>>();
    for (int t = 0; t < TT; t++)
        lstm_step_kernel<<<gS, blk>>>(U2, t, 1);

    // Gather last valid h2 + dense + relu
    dense_out_kernel<<<BB, 128>>>(seq, Wd, bd, out);
}